// round 1
// baseline (speedup 1.0000x reference)
#include <cuda_runtime.h>
#include <cuda_bf16.h>
#include <math.h>

// Problem constants (match reference)
#define N_NODES 50000
#define DIM_IN  128
#define DIM_H   64
#define DIM_OUT 16

// Scratch buffers (allocation-free: __device__ globals)
__device__ __align__(16) float g_bufA[N_NODES * DIM_H];   // gemm outputs
__device__ __align__(16) float g_bufB[N_NODES * DIM_H];   // spmm outputs (d=64)
__device__ __align__(16) float g_bufC[N_NODES * DIM_OUT]; // gemm3 output
__device__ __align__(16) float g_bufD[N_NODES * DIM_OUT]; // spmm3 output

// ---------------------------------------------------------------------------
// Zero kernel (grid-stride float4)
// ---------------------------------------------------------------------------
__global__ void zero_kernel(float4* __restrict__ p, int n4) {
    int i = blockIdx.x * blockDim.x + threadIdx.x;
    int stride = gridDim.x * blockDim.x;
    float4 z = make_float4(0.f, 0.f, 0.f, 0.f);
    for (; i < n4; i += stride) p[i] = z;
}

// ---------------------------------------------------------------------------
// Dense GEMM: out[n, DOUT] = act(in[n, DIN]) @ W[DIN, DOUT]
// TANH_IN applies tanh to the input as it is staged (fuses activation).
// Each thread computes 4 consecutive output columns (float4 accumulate).
// ---------------------------------------------------------------------------
template <int DIN, int DOUT, bool TANH_IN>
__global__ void gemm_kernel(const float* __restrict__ in,
                            const float* __restrict__ W,
                            float* __restrict__ out, int n) {
    constexpr int TPN = DOUT / 4;      // threads per node
    constexpr int NPB = 128 / TPN;     // nodes per block
    constexpr int XPAD = 4;            // bank-conflict padding (floats)

    __shared__ float Ws[DIN * DOUT];
    __shared__ float xs[NPB][DIN + XPAD];

    const int tid = threadIdx.x;
    const int node0 = blockIdx.x * NPB;

    // Stage W (float4)
    #pragma unroll 4
    for (int i = tid; i < DIN * DOUT / 4; i += 128)
        reinterpret_cast<float4*>(Ws)[i] = reinterpret_cast<const float4*>(W)[i];

    // Stage x rows (float4), fusing tanh if requested
    for (int i = tid; i < NPB * (DIN / 4); i += 128) {
        int nn = i / (DIN / 4);
        int kk = i % (DIN / 4);
        float4 v = make_float4(0.f, 0.f, 0.f, 0.f);
        int node = node0 + nn;
        if (node < n)
            v = reinterpret_cast<const float4*>(in + (size_t)node * DIN)[kk];
        if (TANH_IN) {
            v.x = tanhf(v.x); v.y = tanhf(v.y);
            v.z = tanhf(v.z); v.w = tanhf(v.w);
        }
        reinterpret_cast<float4*>(&xs[nn][0])[kk] = v;
    }
    __syncthreads();

    const int local = tid / TPN;   // node within block
    const int jq    = tid % TPN;   // output column quad
    const int node  = node0 + local;

    float4 acc = make_float4(0.f, 0.f, 0.f, 0.f);
    #pragma unroll 8
    for (int k = 0; k < DIN; k++) {
        float  xv = xs[local][k];
        float4 w  = reinterpret_cast<float4*>(Ws)[k * TPN + jq];
        acc.x = fmaf(xv, w.x, acc.x);
        acc.y = fmaf(xv, w.y, acc.y);
        acc.z = fmaf(xv, w.z, acc.z);
        acc.w = fmaf(xv, w.w, acc.w);
    }
    if (node < n)
        reinterpret_cast<float4*>(out + (size_t)node * DOUT)[jq] = acc;
}

// ---------------------------------------------------------------------------
// SpMM d=64: one warp per edge. out[dst] += val * h[src]
// ---------------------------------------------------------------------------
__global__ void spmm64_kernel(const int* __restrict__ src,
                              const int* __restrict__ dst,
                              const float* __restrict__ val,
                              const float* __restrict__ h,
                              float* __restrict__ out, int E) {
    int g = blockIdx.x * blockDim.x + threadIdx.x;
    int e = g >> 5;
    if (e >= E) return;
    int lane = g & 31;
    int s = __ldg(&src[e]);
    int d = __ldg(&dst[e]);
    float v = __ldg(&val[e]);
    const float* hs = h + (size_t)s * 64;
    float* o = out + (size_t)d * 64;
    atomicAdd(&o[lane],      v * __ldg(&hs[lane]));
    atomicAdd(&o[lane + 32], v * __ldg(&hs[lane + 32]));
}

// ---------------------------------------------------------------------------
// SpMM d=16: half-warp (16 lanes) per edge.
// ---------------------------------------------------------------------------
__global__ void spmm16_kernel(const int* __restrict__ src,
                              const int* __restrict__ dst,
                              const float* __restrict__ val,
                              const float* __restrict__ h,
                              float* __restrict__ out, int E) {
    int g = blockIdx.x * blockDim.x + threadIdx.x;
    int e = g >> 4;
    if (e >= E) return;
    int f = g & 15;
    int s = __ldg(&src[e]);
    int d = __ldg(&dst[e]);
    float v = __ldg(&val[e]);
    atomicAdd(&out[(size_t)d * 16 + f], v * __ldg(&h[(size_t)s * 16 + f]));
}

// ---------------------------------------------------------------------------
// Softmax over 16 columns, one thread per node.
// ---------------------------------------------------------------------------
__global__ void softmax16_kernel(const float* __restrict__ in,
                                 float* __restrict__ out, int n) {
    int i = blockIdx.x * blockDim.x + threadIdx.x;
    if (i >= n) return;
    const float4* r = reinterpret_cast<const float4*>(in + (size_t)i * 16);
    float4 a = r[0], b = r[1], c = r[2], d = r[3];
    float v[16] = {a.x,a.y,a.z,a.w, b.x,b.y,b.z,b.w,
                   c.x,c.y,c.z,c.w, d.x,d.y,d.z,d.w};
    float m = v[0];
    #pragma unroll
    for (int k = 1; k < 16; k++) m = fmaxf(m, v[k]);
    float sum = 0.f;
    #pragma unroll
    for (int k = 0; k < 16; k++) { v[k] = __expf(v[k] - m); sum += v[k]; }
    float inv = 1.f / sum;
    float4* w = reinterpret_cast<float4*>(out + (size_t)i * 16);
    w[0] = make_float4(v[0]*inv,  v[1]*inv,  v[2]*inv,  v[3]*inv);
    w[1] = make_float4(v[4]*inv,  v[5]*inv,  v[6]*inv,  v[7]*inv);
    w[2] = make_float4(v[8]*inv,  v[9]*inv,  v[10]*inv, v[11]*inv);
    w[3] = make_float4(v[12]*inv, v[13]*inv, v[14]*inv, v[15]*inv);
}

// ---------------------------------------------------------------------------
// Launch
// ---------------------------------------------------------------------------
extern "C" void kernel_launch(void* const* d_in, const int* in_sizes, int n_in,
                              void* d_out, int out_size) {
    const float* x        = (const float*)d_in[0];
    const int*   edge_src = (const int*)d_in[1];
    const int*   edge_dst = (const int*)d_in[2];
    const float* edge_val = (const float*)d_in[3];
    const float* W1       = (const float*)d_in[4];
    const float* W2       = (const float*)d_in[5];
    const float* W3       = (const float*)d_in[6];
    float* out = (float*)d_out;

    const int N = in_sizes[0] / DIM_IN;   // 50000
    const int E = in_sizes[1];            // 800000

    float *bufA, *bufB, *bufC, *bufD;
    cudaGetSymbolAddress((void**)&bufA, g_bufA);
    cudaGetSymbolAddress((void**)&bufB, g_bufB);
    cudaGetSymbolAddress((void**)&bufC, g_bufC);
    cudaGetSymbolAddress((void**)&bufD, g_bufD);

    // Layer 1: A = x @ W1
    {
        constexpr int NPB = 128 / (DIM_H / 4);  // 8
        gemm_kernel<DIM_IN, DIM_H, false><<<(N + NPB - 1) / NPB, 128>>>(x, W1, bufA, N);
    }
    // B = 0 ; B = spmm(A)
    {
        int n4 = N * DIM_H / 4;
        zero_kernel<<<2048, 256>>>((float4*)bufB, n4);
        long long threads = (long long)E * 32;
        spmm64_kernel<<<(int)((threads + 255) / 256), 256>>>(edge_src, edge_dst, edge_val, bufA, bufB, E);
    }
    // Layer 2: A = tanh(B) @ W2
    {
        constexpr int NPB = 128 / (DIM_H / 4);  // 8
        gemm_kernel<DIM_H, DIM_H, true><<<(N + NPB - 1) / NPB, 128>>>(bufB, W2, bufA, N);
    }
    // B = 0 ; B = spmm(A)
    {
        int n4 = N * DIM_H / 4;
        zero_kernel<<<2048, 256>>>((float4*)bufB, n4);
        long long threads = (long long)E * 32;
        spmm64_kernel<<<(int)((threads + 255) / 256), 256>>>(edge_src, edge_dst, edge_val, bufA, bufB, E);
    }
    // Layer 3: C = B @ W3
    {
        constexpr int NPB = 128 / (DIM_OUT / 4);  // 32
        gemm_kernel<DIM_H, DIM_OUT, false><<<(N + NPB - 1) / NPB, 128>>>(bufB, W3, bufC, N);
    }
    // D = 0 ; D = spmm(C)
    {
        int n4 = N * DIM_OUT / 4;
        zero_kernel<<<1024, 256>>>((float4*)bufD, n4);
        long long threads = (long long)E * 16;
        spmm16_kernel<<<(int)((threads + 255) / 256), 256>>>(edge_src, edge_dst, edge_val, bufC, bufD, E);
    }
    // Softmax
    softmax16_kernel<<<(N + 255) / 256, 256>>>(bufD, out, N);
}

// round 8
// speedup vs baseline: 1.8752x; 1.8752x over previous
#include <cuda_runtime.h>
#include <cuda_bf16.h>
#include <math.h>

#define N_NODES 50000
#define DIM_IN  128
#define DIM_H   64
#define DIM_OUT 16

// Scratch (allocation-free: __device__ globals)
__device__ __align__(16) float g_A[N_NODES * DIM_H];    // gemm1 out
__device__ __align__(16) float g_B[N_NODES * DIM_H];    // spmm64 out
__device__ __align__(16) float g_C[N_NODES * DIM_OUT];  // tanh(B)@W23
__device__ __align__(16) float g_U[N_NODES * DIM_OUT];  // spmm16 #1 out
__device__ __align__(16) float g_D[N_NODES * DIM_OUT];  // spmm16 #2 out
__device__ __align__(16) float g_W23[DIM_H * DIM_OUT];  // W2@W3

// ---------------------------------------------------------------------------
// Vector float atomic-add (no return): PTX red.global.add.v4.f32 (sm_90+)
// ---------------------------------------------------------------------------
__device__ __forceinline__ void red_add_v4(float* addr, float4 v) {
    asm volatile("red.global.add.v4.f32 [%0], {%1,%2,%3,%4};"
                 :: "l"(addr), "f"(v.x), "f"(v.y), "f"(v.z), "f"(v.w)
                 : "memory");
}

// ---------------------------------------------------------------------------
// Fused zero kernel: zeroes B (d=64 accum), U and D (d=16 accums) in one pass.
// ---------------------------------------------------------------------------
__global__ void zero3_kernel(float4* __restrict__ b, int nb4,
                             float4* __restrict__ u, int nu4,
                             float4* __restrict__ d, int nd4) {
    int i = blockIdx.x * blockDim.x + threadIdx.x;
    int stride = gridDim.x * blockDim.x;
    float4 z = make_float4(0.f, 0.f, 0.f, 0.f);
    for (int k = i; k < nb4; k += stride) b[k] = z;
    for (int k = i; k < nu4; k += stride) u[k] = z;
    for (int k = i; k < nd4; k += stride) d[k] = z;
}

// ---------------------------------------------------------------------------
// W23 = W2[64,64] @ W3[64,16]   (tiny, one-off)
// ---------------------------------------------------------------------------
__global__ void w23_kernel(const float* __restrict__ W2,
                           const float* __restrict__ W3,
                           float* __restrict__ W23) {
    int i = blockIdx.x * blockDim.x + threadIdx.x;
    if (i >= DIM_H * DIM_OUT) return;
    int r = i / DIM_OUT, c = i % DIM_OUT;
    float s = 0.f;
    #pragma unroll 8
    for (int k = 0; k < DIM_H; k++)
        s = fmaf(W2[r * DIM_H + k], W3[k * DIM_OUT + c], s);
    W23[i] = s;
}

// ---------------------------------------------------------------------------
// Register-tiled GEMM: out[n, DOUT] = in[n, DIN] @ W[DIN, DOUT]
// 128 threads; 32 nodes/block; thread = 4 nodes x 4 cols (16 FMA per k,
// fed by 1 LDS.128 from transposed x + 1 LDS.128 from W).
// ---------------------------------------------------------------------------
template <int DIN, int DOUT>
__global__ void gemm_tiled(const float* __restrict__ in,
                           const float* __restrict__ W,
                           float* __restrict__ out, int n) {
    constexpr int QUADS = DOUT / 4;      // 16
    constexpr int SLOTS = 128 / QUADS;   // 8
    constexpr int NPB   = SLOTS * 4;     // 32 nodes/block
    constexpr int KQ    = DIN / 4;

    __shared__ __align__(16) float Ws[DIN * DOUT];   // 32KB @128x64
    __shared__ __align__(16) float xs[DIN][NPB];     // 16KB (transposed)

    const int tid = threadIdx.x;
    const int node0 = blockIdx.x * NPB;

    #pragma unroll 4
    for (int i = tid; i < DIN * DOUT / 4; i += 128)
        reinterpret_cast<float4*>(Ws)[i] = reinterpret_cast<const float4*>(W)[i];

    for (int i = tid; i < NPB * KQ; i += 128) {
        int nn = i / KQ;
        int kk = i % KQ;
        int node = node0 + nn;
        float4 v = make_float4(0.f, 0.f, 0.f, 0.f);
        if (node < n)
            v = reinterpret_cast<const float4*>(in + (size_t)node * DIN)[kk];
        xs[kk * 4 + 0][nn] = v.x;
        xs[kk * 4 + 1][nn] = v.y;
        xs[kk * 4 + 2][nn] = v.z;
        xs[kk * 4 + 3][nn] = v.w;
    }
    __syncthreads();

    const int quad  = tid % QUADS;
    const int nbase = (tid / QUADS) * 4;

    float4 a0 = {}, a1 = {}, a2 = {}, a3 = {};
    #pragma unroll 4
    for (int k = 0; k < DIN; k++) {
        float4 xv = *reinterpret_cast<const float4*>(&xs[k][nbase]);
        float4 w  = reinterpret_cast<const float4*>(Ws)[k * QUADS + quad];
        a0.x = fmaf(xv.x, w.x, a0.x); a0.y = fmaf(xv.x, w.y, a0.y);
        a0.z = fmaf(xv.x, w.z, a0.z); a0.w = fmaf(xv.x, w.w, a0.w);
        a1.x = fmaf(xv.y, w.x, a1.x); a1.y = fmaf(xv.y, w.y, a1.y);
        a1.z = fmaf(xv.y, w.z, a1.z); a1.w = fmaf(xv.y, w.w, a1.w);
        a2.x = fmaf(xv.z, w.x, a2.x); a2.y = fmaf(xv.z, w.y, a2.y);
        a2.z = fmaf(xv.z, w.z, a2.z); a2.w = fmaf(xv.z, w.w, a2.w);
        a3.x = fmaf(xv.w, w.x, a3.x); a3.y = fmaf(xv.w, w.y, a3.y);
        a3.z = fmaf(xv.w, w.z, a3.z); a3.w = fmaf(xv.w, w.w, a3.w);
    }
    float4 accs[4] = {a0, a1, a2, a3};
    #pragma unroll
    for (int i = 0; i < 4; i++) {
        int node = node0 + nbase + i;
        if (node < n)
            reinterpret_cast<float4*>(out + (size_t)node * DOUT)[quad] = accs[i];
    }
}

// ---------------------------------------------------------------------------
// Small GEMM with fused tanh on input: out[n,16] = tanh(in[n,64]) @ W[64,16]
// ---------------------------------------------------------------------------
__global__ void gemm_tanh16(const float* __restrict__ in,
                            const float* __restrict__ W,
                            float* __restrict__ out, int n) {
    constexpr int DIN = DIM_H, DOUT = DIM_OUT;
    constexpr int TPN = DOUT / 4;      // 4
    constexpr int NPB = 128 / TPN;     // 32
    __shared__ __align__(16) float Ws[DIN * DOUT];
    __shared__ __align__(16) float xs[NPB][DIN + 4];

    const int tid = threadIdx.x;
    const int node0 = blockIdx.x * NPB;

    for (int i = tid; i < DIN * DOUT / 4; i += 128)
        reinterpret_cast<float4*>(Ws)[i] = reinterpret_cast<const float4*>(W)[i];

    for (int i = tid; i < NPB * (DIN / 4); i += 128) {
        int nn = i / (DIN / 4);
        int kk = i % (DIN / 4);
        float4 v = make_float4(0.f, 0.f, 0.f, 0.f);
        int node = node0 + nn;
        if (node < n)
            v = reinterpret_cast<const float4*>(in + (size_t)node * DIN)[kk];
        v.x = tanhf(v.x); v.y = tanhf(v.y); v.z = tanhf(v.z); v.w = tanhf(v.w);
        reinterpret_cast<float4*>(&xs[nn][0])[kk] = v;
    }
    __syncthreads();

    const int local = tid / TPN;
    const int jq    = tid % TPN;
    const int node  = node0 + local;

    float4 acc = make_float4(0.f, 0.f, 0.f, 0.f);
    #pragma unroll 8
    for (int k = 0; k < DIN; k++) {
        float  xv = xs[local][k];
        float4 w  = reinterpret_cast<float4*>(Ws)[k * TPN + jq];
        acc.x = fmaf(xv, w.x, acc.x);
        acc.y = fmaf(xv, w.y, acc.y);
        acc.z = fmaf(xv, w.z, acc.z);
        acc.w = fmaf(xv, w.w, acc.w);
    }
    if (node < n)
        reinterpret_cast<float4*>(out + (size_t)node * DOUT)[jq] = acc;
}

// ---------------------------------------------------------------------------
// SpMM d=64: 8 threads/edge, 2 quads per thread (q and q+8).
// Per edge: 24 index LDG (vs 48 at 16t/e), 2 gathers + 2 v4 reds per thread.
// ---------------------------------------------------------------------------
__global__ void spmm64_v4(const int* __restrict__ src,
                          const int* __restrict__ dst,
                          const float* __restrict__ val,
                          const float* __restrict__ h,
                          float* __restrict__ out, int E) {
    int g = blockIdx.x * blockDim.x + threadIdx.x;
    int e = g >> 3;
    if (e >= E) return;
    int q = g & 7;
    int s = __ldg(&src[e]);
    int d = __ldg(&dst[e]);
    float v = __ldg(&val[e]);
    const float4* hs = reinterpret_cast<const float4*>(h + (size_t)s * 64);
    float4 hv0 = __ldg(hs + q);
    float4 hv1 = __ldg(hs + q + 8);
    float4 m0 = make_float4(v * hv0.x, v * hv0.y, v * hv0.z, v * hv0.w);
    float4 m1 = make_float4(v * hv1.x, v * hv1.y, v * hv1.z, v * hv1.w);
    float* o = out + (size_t)d * 64;
    red_add_v4(o + q * 4, m0);
    red_add_v4(o + (q + 8) * 4, m1);
}

// ---------------------------------------------------------------------------
// SpMM d=16: 4 threads/edge.
// ---------------------------------------------------------------------------
__global__ void spmm16_v4(const int* __restrict__ src,
                          const int* __restrict__ dst,
                          const float* __restrict__ val,
                          const float* __restrict__ h,
                          float* __restrict__ out, int E) {
    int g = blockIdx.x * blockDim.x + threadIdx.x;
    int e = g >> 2;
    if (e >= E) return;
    int q = g & 3;
    int s = __ldg(&src[e]);
    int d = __ldg(&dst[e]);
    float v = __ldg(&val[e]);
    float4 hv = __ldg(reinterpret_cast<const float4*>(h + (size_t)s * 16) + q);
    float4 m = make_float4(v * hv.x, v * hv.y, v * hv.z, v * hv.w);
    red_add_v4(out + (size_t)d * 16 + q * 4, m);
}

// ---------------------------------------------------------------------------
// Softmax over 16 columns, one thread per node.
// ---------------------------------------------------------------------------
__global__ void softmax16_kernel(const float* __restrict__ in,
                                 float* __restrict__ out, int n) {
    int i = blockIdx.x * blockDim.x + threadIdx.x;
    if (i >= n) return;
    const float4* r = reinterpret_cast<const float4*>(in + (size_t)i * 16);
    float4 a = r[0], b = r[1], c = r[2], d = r[3];
    float v[16] = {a.x,a.y,a.z,a.w, b.x,b.y,b.z,b.w,
                   c.x,c.y,c.z,c.w, d.x,d.y,d.z,d.w};
    float m = v[0];
    #pragma unroll
    for (int k = 1; k < 16; k++) m = fmaxf(m, v[k]);
    float sum = 0.f;
    #pragma unroll
    for (int k = 0; k < 16; k++) { v[k] = __expf(v[k] - m); sum += v[k]; }
    float inv = 1.f / sum;
    float4* w = reinterpret_cast<float4*>(out + (size_t)i * 16);
    w[0] = make_float4(v[0]*inv,  v[1]*inv,  v[2]*inv,  v[3]*inv);
    w[1] = make_float4(v[4]*inv,  v[5]*inv,  v[6]*inv,  v[7]*inv);
    w[2] = make_float4(v[8]*inv,  v[9]*inv,  v[10]*inv, v[11]*inv);
    w[3] = make_float4(v[12]*inv, v[13]*inv, v[14]*inv, v[15]*inv);
}

// ---------------------------------------------------------------------------
// Launch
// ---------------------------------------------------------------------------
extern "C" void kernel_launch(void* const* d_in, const int* in_sizes, int n_in,
                              void* d_out, int out_size) {
    const float* x        = (const float*)d_in[0];
    const int*   edge_src = (const int*)d_in[1];
    const int*   edge_dst = (const int*)d_in[2];
    const float* edge_val = (const float*)d_in[3];
    const float* W1       = (const float*)d_in[4];
    const float* W2       = (const float*)d_in[5];
    const float* W3       = (const float*)d_in[6];
    float* out = (float*)d_out;

    const int N = in_sizes[0] / DIM_IN;   // 50000
    const int E = in_sizes[1];            // 800000

    float *A, *B, *C, *U, *D, *W23;
    cudaGetSymbolAddress((void**)&A, g_A);
    cudaGetSymbolAddress((void**)&B, g_B);
    cudaGetSymbolAddress((void**)&C, g_C);
    cudaGetSymbolAddress((void**)&U, g_U);
    cudaGetSymbolAddress((void**)&D, g_D);
    cudaGetSymbolAddress((void**)&W23, g_W23);

    // Prologue: fused zeroing of all accumulators + tiny W23 GEMM
    zero3_kernel<<<2048, 256>>>((float4*)B, N * DIM_H / 4,
                                (float4*)U, N * DIM_OUT / 4,
                                (float4*)D, N * DIM_OUT / 4);
    w23_kernel<<<4, 256>>>(W2, W3, W23);

    // A = x @ W1
    gemm_tiled<DIM_IN, DIM_H><<<(N + 31) / 32, 128>>>(x, W1, A, N);

    // B += spmm(A)   [d=64]  (8 threads/edge)
    {
        long long threads = (long long)E * 8;
        spmm64_v4<<<(int)((threads + 255) / 256), 256>>>(edge_src, edge_dst, edge_val, A, B, E);
    }

    // C = tanh(B) @ W23   [50k,16]
    gemm_tanh16<<<(N + 31) / 32, 128>>>(B, W23, C, N);

    // U += spmm(C)   [d=16]
    {
        long long threads = (long long)E * 4;
        spmm16_v4<<<(int)((threads + 255) / 256), 256>>>(edge_src, edge_dst, edge_val, C, U, E);
    }

    // D += spmm(U)   [d=16]
    {
        long long threads = (long long)E * 4;
        spmm16_v4<<<(int)((threads + 255) / 256), 256>>>(edge_src, edge_dst, edge_val, U, D, E);
    }

    // out = softmax(D)
    softmax16_kernel<<<(N + 255) / 256, 256>>>(D, out, N);
}